// round 16
// baseline (speedup 1.0000x reference)
#include <cuda_runtime.h>
#include <cuda_bf16.h>
#include <cstdint>

#define DD 64
#define HH 256
#define ROWS 64            // rows per CTA
#define THREADS 512        // 16 warps = 4 row-stripes x 4 jj-parts

// padded bf16 strides (elements)
#define YSTR  136
#define W1STR 136
#define W2STR 520

#define W1IMG_BYTES (HH * W1STR * 2)   // 69632
#define W2IMG_BYTES (DD * W2STR * 2)   // 66560

#define SM_Y   0
#define SM_W1  (SM_Y  + ROWS * YSTR * 2)          // 17408
#define SM_W2  (SM_W1 + W1IMG_BYTES)              // 87040
#define SM_Z   (SM_W2 + W2IMG_BYTES)              // 153600
#define SM_S   (SM_Z + HH * 4)
#define SM_B2  (SM_S + HH * 4)
#define SMEM_TOTAL (SM_B2 + DD * 4 + 16)

// post-mainloop reuse of [SM_Y .. SM_W2): partials + div partials
#define PSTR   68
#define SM_P   0                            // float [4][64][PSTR] = 69632 B
#define SM_DV  (4 * ROWS * PSTR * 4)        // float [4][64] = 1024 B

// gmem images, cooperatively converted each launch
__device__ __align__(16) unsigned char g_w1img[W1IMG_BYTES];
__device__ __align__(16) unsigned char g_w2img[W2IMG_BYTES];
__device__ __align__(16) float g_z[HH];
__device__ __align__(16) float g_s[HH];
__device__ __align__(16) float g_b2[DD];
__device__ unsigned g_ctr = 0;     // grid-sync ticket counter (replay-safe)

__device__ __forceinline__ uint32_t smem_u32(const void* p) {
    uint32_t a;
    asm("{ .reg .u64 t; cvta.to.shared.u64 t, %1; cvt.u32.u64 %0, t; }" : "=r"(a) : "l"(p));
    return a;
}
__device__ __forceinline__ float tanh_ap(float x) {
    float r; asm("tanh.approx.f32 %0, %1;" : "=f"(r) : "f"(x)); return r;
}
__device__ __forceinline__ uint32_t packbf(float lo, float hi) {
    uint32_t r;
    asm("cvt.rn.bf16x2.f32 %0, %1, %2;" : "=r"(r) : "f"(hi), "f"(lo));
    return r;   // low 16 = lo operand
}
__device__ __forceinline__ float truncbf(uint32_t u) {
    return __uint_as_float(u & 0xFFFF0000u);
}
__device__ __forceinline__ void mma_bf16(float c[4], const uint32_t a[4], const uint32_t b[2]) {
    asm volatile("mma.sync.aligned.m16n8k16.row.col.f32.bf16.bf16.f32 "
        "{%0,%1,%2,%3}, {%4,%5,%6,%7}, {%8,%9}, {%0,%1,%2,%3};"
        : "+f"(c[0]), "+f"(c[1]), "+f"(c[2]), "+f"(c[3])
        : "r"(a[0]), "r"(a[1]), "r"(a[2]), "r"(a[3]), "r"(b[0]), "r"(b[1]));
}
#define LDM4(R, addr) asm volatile( \
    "ldmatrix.sync.aligned.m8n8.x4.shared.b16 {%0,%1,%2,%3}, [%4];" \
    : "=r"((R)[0]), "=r"((R)[1]), "=r"((R)[2]), "=r"((R)[3]) : "r"(addr))

__global__ __launch_bounds__(THREADS, 1)
void ode_mma(const float* __restrict__ tptr, const float* __restrict__ y,
             const float* __restrict__ W1, const float* __restrict__ b1,
             const float* __restrict__ wt, const float* __restrict__ W2,
             const float* __restrict__ b2, float* __restrict__ out)
{
    extern __shared__ char smc[];
    float* sz  = (float*)(smc + SM_Z);
    float* ss  = (float*)(smc + SM_S);
    float* sbb = (float*)(smc + SM_B2);

    const uint32_t sbase = smem_u32(smc);
    const int tid  = threadIdx.x;
    const int lane = tid & 31;
    const int warp = tid >> 5;
    const int stripe = warp & 3;          // 16-row stripe
    const int part   = warp >> 2;         // jj quarter (0..3)
    const int cta = blockIdx.x;

    // ======== phase A: cooperative 1/128 slice conversion -> gmem images ========
    {
        __nv_bfloat16* w1i = (__nv_bfloat16*)g_w1img;
        __nv_bfloat16* w2i = (__nv_bfloat16*)g_w2img;
        if (tid < 128) {                  // W1 slice: 128 elems
            const int g = cta * 128 + tid;
            const int d = g >> 8, j = g & 255;
            float v = W1[g];
            __nv_bfloat16 h = __float2bfloat16(v);
            w1i[j * W1STR + d]      = h;
            w1i[j * W1STR + 64 + d] = __float2bfloat16(v - __bfloat162float(h));
        } else if (tid < 256) {           // W2 slice: 128 elems
            const int g = cta * 128 + (tid - 128);
            const int hr = g >> 6, n = g & 63;
            float v = W2[g];
            __nv_bfloat16 h = __float2bfloat16(v);
            w2i[n * W2STR + hr]       = h;
            w2i[n * W2STR + 256 + hr] = __float2bfloat16(v - __bfloat162float(h));
        } else if (tid < 320) {           // s_j: 2 j per CTA, warp-reduced
            const int j = cta * 2 + ((tid - 256) >> 5);
            const int d = tid & 31;
            float p = W1[d * HH + j] * W2[j * DD + d]
                    + W1[(d + 32) * HH + j] * W2[j * DD + d + 32];
            p += __shfl_xor_sync(0xffffffffu, p, 1);
            p += __shfl_xor_sync(0xffffffffu, p, 2);
            p += __shfl_xor_sync(0xffffffffu, p, 4);
            p += __shfl_xor_sync(0xffffffffu, p, 8);
            p += __shfl_xor_sync(0xffffffffu, p, 16);
            if (d == 0) g_s[j] = p;
        } else if (tid < 322) {           // z: 2 per CTA
            const int j = cta * 2 + (tid - 320);
            g_z[j] = tptr[0] * wt[j] + b1[j];
        } else if (tid == 322 && cta < DD) {
            g_b2[cta] = b2[cta];
        }
    }
    __syncthreads();                       // CTA's slice writes issued

    unsigned target = 0;
    if (tid == 0) {                        // release + arrive (cg grid.sync pattern)
        __threadfence();
        unsigned tk = atomicAdd(&g_ctr, 1u);
        target = (tk / gridDim.x + 1u) * gridDim.x;
    }

    // ---- Y conversion (own tile; overlaps other CTAs' phase A) ----
    {
        const float2* yb = (const float2*)(y + (size_t)cta * ROWS * DD);
        uint32_t* sy32 = (uint32_t*)(smc + SM_Y);
        #pragma unroll
        for (int i = tid; i < ROWS * DD / 2; i += THREADS) {
            const int r = i >> 5, dp = (i & 31);
            float2 v = yb[i];
            uint32_t u0 = __float_as_uint(v.x), u1 = __float_as_uint(v.y);
            sy32[r * (YSTR / 2) + dp]      = __byte_perm(u0, u1, 0x7632);
            sy32[r * (YSTR / 2) + 32 + dp] = packbf(v.x - truncbf(u0), v.y - truncbf(u1));
        }
    }

    if (tid == 0) {                        // wait for all CTAs' slices
        while (atomicAdd(&g_ctr, 0u) < target) { }
        __threadfence();
    }
    __syncthreads();

    // ======== phase B: flat L2-hot image copies (bypass L1 via ldcg) ========
    {
        const float4* s1 = (const float4*)g_w1img;
        float4* d1 = (float4*)(smc + SM_W1);
        #pragma unroll
        for (int i = tid; i < W1IMG_BYTES / 16; i += THREADS) d1[i] = __ldcg(s1 + i);
        const float4* s2 = (const float4*)g_w2img;
        float4* d2 = (float4*)(smc + SM_W2);
        #pragma unroll
        for (int i = tid; i < W2IMG_BYTES / 16; i += THREADS) d2[i] = __ldcg(s2 + i);
        if (tid < HH) { sz[tid] = __ldcg(&g_z[tid]); ss[tid] = __ldcg(&g_s[tid]); }
        if (tid < DD) sbb[tid] = __ldcg(&g_b2[tid]);
    }
    __syncthreads();

    // ======== per-warp: 16-row stripe, quarter of hidden dim ========
    const int r0 = stripe * 16;

    uint32_t yhi[4][4], ylo[4][4];
    {
        const int arow = r0 + (lane & 7) + ((lane >> 3) & 1) * 8;
        const int acol = ((lane >> 4) & 1) * 8;
        const uint32_t abase = sbase + SM_Y + (uint32_t)arow * (YSTR * 2);
        #pragma unroll
        for (int kk = 0; kk < 4; kk++) {
            LDM4(yhi[kk], abase + (uint32_t)(kk * 16 + acol) * 2);
            LDM4(ylo[kk], abase + (uint32_t)(64 + kk * 16 + acol) * 2);
        }
    }

    float acc2[8][4];
    #pragma unroll
    for (int t = 0; t < 8; t++)
        #pragma unroll
        for (int i = 0; i < 4; i++) acc2[t][i] = 0.f;
    float dvlo = 0.f, dvhi = 0.f;

    const int qq = (lane & 3) * 2;
    const uint32_t w1lo_off = (uint32_t)(lane & 7) * (W1STR * 2)
        + (uint32_t)(((lane >> 3) & 1) * 8 + ((lane >> 4) & 1) * 64) * 2;
    const uint32_t w2lo_off = (uint32_t)(lane & 7) * (W2STR * 2)
        + (uint32_t)(((lane >> 3) & 1) * 8 + ((lane >> 4) & 1) * 256) * 2;

    const int jjBeg = part * 4;
    #pragma unroll
    for (int u = 0; u < 4; u++) {
        const int jj = jjBeg + u;

        // ---- GEMM1: 3 independent chains per n8 fragment ----
        float cfA[2][4], cfB[2][4], cfC[2][4];
        #pragma unroll
        for (int p = 0; p < 2; p++) {
            const int j0p = jj * 16 + p * 8;
            float2 zz = *(const float2*)(sz + j0p + qq);
            cfA[p][0] = zz.x; cfA[p][1] = zz.y; cfA[p][2] = zz.x; cfA[p][3] = zz.y;
            #pragma unroll
            for (int i = 0; i < 4; i++) { cfB[p][i] = 0.f; cfC[p][i] = 0.f; }

            const uint32_t bbase = sbase + SM_W1 + (uint32_t)j0p * (W1STR * 2) + w1lo_off;
            #pragma unroll
            for (int kk = 0; kk < 4; kk++) {
                uint32_t bf[4];                      // [0:2)=hi, [2:4)=lo
                LDM4(bf, bbase + (uint32_t)kk * 32);
                mma_bf16(cfA[p], yhi[kk], bf);
                mma_bf16(cfB[p], ylo[kk], bf);
                mma_bf16(cfC[p], yhi[kk], bf + 2);
            }
        }

        // ---- epilogue-1: tanh + cheap truncation split ----
        uint32_t Ah[4], Al[4];
        float hv[2][4];
        #pragma unroll
        for (int p = 0; p < 2; p++) {
            float h0 = tanh_ap((cfA[p][0] + cfB[p][0]) + cfC[p][0]);
            float h1 = tanh_ap((cfA[p][1] + cfB[p][1]) + cfC[p][1]);
            float h2 = tanh_ap((cfA[p][2] + cfB[p][2]) + cfC[p][2]);
            float h3 = tanh_ap((cfA[p][3] + cfB[p][3]) + cfC[p][3]);
            hv[p][0] = h0; hv[p][1] = h1; hv[p][2] = h2; hv[p][3] = h3;
            uint32_t u0 = __float_as_uint(h0), u1 = __float_as_uint(h1);
            uint32_t u2 = __float_as_uint(h2), u3 = __float_as_uint(h3);
            Ah[p * 2 + 0] = __byte_perm(u0, u1, 0x7632);
            Ah[p * 2 + 1] = __byte_perm(u2, u3, 0x7632);
            Al[p * 2 + 0] = packbf(h0 - truncbf(u0), h1 - truncbf(u1));
            Al[p * 2 + 1] = packbf(h2 - truncbf(u2), h3 - truncbf(u3));
        }

        // ---- GEMM2: 8 independent chains ----
        const uint32_t b2base = sbase + SM_W2 + (uint32_t)(jj * 16) * 2 + w2lo_off;
        #pragma unroll
        for (int t = 0; t < 8; t++) {
            uint32_t bf[4];
            LDM4(bf, b2base + (uint32_t)t * 8 * (W2STR * 2));
            mma_bf16(acc2[t], Ah, bf);
            mma_bf16(acc2[t], Al, bf);
            mma_bf16(acc2[t], Ah, bf + 2);
        }

        // ---- divergence FMAs ----
        #pragma unroll
        for (int p = 0; p < 2; p++) {
            float2 sv = *(const float2*)(ss + jj * 16 + p * 8 + qq);
            dvlo += (1.f - hv[p][0] * hv[p][0]) * sv.x + (1.f - hv[p][1] * hv[p][1]) * sv.y;
            dvhi += (1.f - hv[p][2] * hv[p][2]) * sv.x + (1.f - hv[p][3] * hv[p][3]) * sv.y;
        }
    }

    // ---- combine the 4 jj-quarters via smem ----
    __syncthreads();
    {
        float* sP  = (float*)(smc + SM_P);   // [4][64][PSTR]
        float* sDv = (float*)(smc + SM_DV);  // [4][64]
        const int rA = r0 + (lane >> 2);
        const int rB = rA + 8;
        float* pA = sP + ((size_t)part * ROWS + rA) * PSTR + qq;
        float* pB = sP + ((size_t)part * ROWS + rB) * PSTR + qq;
        #pragma unroll
        for (int t = 0; t < 8; t++) {
            *(float2*)(pA + t * 8) = make_float2(acc2[t][0], acc2[t][1]);
            *(float2*)(pB + t * 8) = make_float2(acc2[t][2], acc2[t][3]);
        }
        dvlo += __shfl_xor_sync(0xffffffffu, dvlo, 1);
        dvlo += __shfl_xor_sync(0xffffffffu, dvlo, 2);
        dvhi += __shfl_xor_sync(0xffffffffu, dvhi, 1);
        dvhi += __shfl_xor_sync(0xffffffffu, dvhi, 2);
        if ((lane & 3) == 0) {
            sDv[part * ROWS + rA] = dvlo;
            sDv[part * ROWS + rB] = dvhi;
        }
    }
    __syncthreads();

    // ---- final: sum 4 partials + b2 -> out ----
    {
        const float* sP  = (const float*)(smc + SM_P);
        const float* sDv = (const float*)(smc + SM_DV);
        const int r  = tid >> 3;             // 0..63
        const int c0 = (tid & 7) * 8;
        float* op = out + (size_t)(cta * ROWS + r) * (DD + 1);
        #pragma unroll
        for (int i = 0; i < 2; i++) {
            const int c = c0 + i * 4;
            float4 a0 = *(const float4*)(sP + (size_t)(0 * ROWS + r) * PSTR + c);
            float4 a1 = *(const float4*)(sP + (size_t)(1 * ROWS + r) * PSTR + c);
            float4 a2 = *(const float4*)(sP + (size_t)(2 * ROWS + r) * PSTR + c);
            float4 a3 = *(const float4*)(sP + (size_t)(3 * ROWS + r) * PSTR + c);
            float4 bb = *(const float4*)(sbb + c);
            op[c + 0] = ((a0.x + a1.x) + (a2.x + a3.x)) + bb.x;
            op[c + 1] = ((a0.y + a1.y) + (a2.y + a3.y)) + bb.y;
            op[c + 2] = ((a0.z + a1.z) + (a2.z + a3.z)) + bb.z;
            op[c + 3] = ((a0.w + a1.w) + (a2.w + a3.w)) + bb.w;
        }
        if ((tid & 7) == 0)
            op[DD] = -((sDv[r] + sDv[ROWS + r]) + (sDv[2 * ROWS + r] + sDv[3 * ROWS + r]));
    }
}

extern "C" void kernel_launch(void* const* d_in, const int* in_sizes, int n_in,
                              void* d_out, int out_size) {
    const float* t  = (const float*)d_in[0];
    const float* y  = (const float*)d_in[1];
    const float* W1 = (const float*)d_in[2];
    const float* b1 = (const float*)d_in[3];
    const float* wt = (const float*)d_in[4];
    const float* W2 = (const float*)d_in[5];
    const float* b2 = (const float*)d_in[6];
    float* out = (float*)d_out;

    const int n = in_sizes[1] / DD;          // 8192
    const int blocks = n / ROWS;             // 128 (< 148 SMs: single wave, spin-safe)

    cudaFuncSetAttribute(ode_mma,
                         cudaFuncAttributeMaxDynamicSharedMemorySize, SMEM_TOTAL);
    ode_mma<<<blocks, THREADS, SMEM_TOTAL>>>(t, y, W1, b1, wt, W2, b2, out);
}